// round 1
// baseline (speedup 1.0000x reference)
#include <cuda_runtime.h>
#include <cstdint>

// Problem constants
#define B_DIM   64
#define N_DIM   512
#define M_ROWS  (B_DIM * N_DIM)     // 32768
#define EMB     1024
#define NKP     17
#define APP_F   (EMB + NKP)         // 1041
#define ST_F    (4 + 3 * NKP)       // 55
#define KTOT    (APP_F + ST_F)      // 1096
#define KPAD    1104                // next multiple of 16
#define TOK     1024

// GEMM tiling
#define BM 128
#define BN 128
#define BK 16

// Scratch (allowed: __device__ globals, no allocation)
__device__ float g_Wt[KPAD * TOK];   // K-major weights: g_Wt[k*TOK + t]
__device__ float g_bias[TOK];        // app_b + st_b

// ---------------------------------------------------------------------------
// Prologue: build K-major fused weight matrix + fused bias.
// app_W: [TOK, APP_F] row-major; st_W: [TOK, ST_F] row-major.
// ---------------------------------------------------------------------------
__global__ void prep_kernel(const float* __restrict__ app_W,
                            const float* __restrict__ app_b,
                            const float* __restrict__ st_W,
                            const float* __restrict__ st_b)
{
    int tid0   = blockIdx.x * blockDim.x + threadIdx.x;
    int stride = gridDim.x * blockDim.x;

    if (tid0 < TOK) g_bias[tid0] = app_b[tid0] + st_b[tid0];

    for (int i = tid0; i < KPAD * TOK; i += stride) {
        int k = i / TOK;
        int t = i - k * TOK;
        float v = 0.0f;
        if (k < APP_F)      v = app_W[t * APP_F + k];
        else if (k < KTOT)  v = st_W[t * ST_F + (k - APP_F)];
        g_Wt[i] = v;
    }
}

// ---------------------------------------------------------------------------
// Fused masked GEMM: out[r, t] = mask[r] ? feat[r,:] . Wt[:,t] + bias[t] : 0
// feat[r,:] = [emb(1024) | vis(17) | bbox(4) | kp(51)] gathered on the fly.
// 128x128 block tile, 16-deep K tile, 256 threads, 8x8 per-thread microtile.
// ---------------------------------------------------------------------------
__global__ __launch_bounds__(256, 2)
void gemm_kernel(const float* __restrict__ emb,
                 const float* __restrict__ vis,
                 const float* __restrict__ bbox,
                 const float* __restrict__ kp,
                 const unsigned int* __restrict__ mask,
                 float* __restrict__ out)
{
    __shared__ float As[BK][BM];
    __shared__ float Bs[BK][BN];

    const int tid  = threadIdx.x;
    const int tx   = tid & 15;          // 0..15 -> column microtile
    const int ty   = tid >> 4;          // 0..15 -> row microtile
    const int row0 = blockIdx.y * BM;
    const int col0 = blockIdx.x * BN;

    // A-tile loader mapping: 256 threads load 128 rows x 16 k (8 floats each)
    const int lrow = tid >> 1;          // 0..127
    const int lk   = (tid & 1) * 8;     // 0 or 8
    const int r    = row0 + lrow;

    // B-tile loader mapping: 16 k-rows x 128 t (8 floats each, coalesced)
    const int bk = tid >> 4;            // 0..15
    const int bt = (tid & 15) * 8;      // 0..120

    float acc[8][8];
    #pragma unroll
    for (int i = 0; i < 8; i++)
        #pragma unroll
        for (int j = 0; j < 8; j++)
            acc[i][j] = 0.0f;

    for (int k0 = 0; k0 < KPAD; k0 += BK) {
        // ---- load A tile (transposed into As[k][m]) ----
        if (k0 + BK <= EMB) {
            // fast path: entirely inside embeddings, vectorized
            const float4* s = reinterpret_cast<const float4*>(emb + r * EMB + k0 + lk);
            float4 v0 = s[0];
            float4 v1 = s[1];
            As[lk + 0][lrow] = v0.x; As[lk + 1][lrow] = v0.y;
            As[lk + 2][lrow] = v0.z; As[lk + 3][lrow] = v0.w;
            As[lk + 4][lrow] = v1.x; As[lk + 5][lrow] = v1.y;
            As[lk + 6][lrow] = v1.z; As[lk + 7][lrow] = v1.w;
        } else {
            // tail: gather from vis / bbox / kp, zero-pad past KTOT
            #pragma unroll
            for (int j = 0; j < 8; j++) {
                int k = k0 + lk + j;
                float v;
                if (k < EMB)              v = emb[r * EMB + k];
                else if (k < APP_F)       v = vis[r * NKP + (k - EMB)];
                else if (k < APP_F + 4)   v = bbox[r * 4 + (k - APP_F)];
                else if (k < KTOT)        v = kp[r * (3 * NKP) + (k - APP_F - 4)];
                else                      v = 0.0f;
                As[lk + j][lrow] = v;
            }
        }

        // ---- load B tile (already K-major, coalesced float4) ----
        {
            const float4* s = reinterpret_cast<const float4*>(g_Wt + (k0 + bk) * TOK + col0 + bt);
            float4 v0 = s[0];
            float4 v1 = s[1];
            *reinterpret_cast<float4*>(&Bs[bk][bt])     = v0;
            *reinterpret_cast<float4*>(&Bs[bk][bt + 4]) = v1;
        }

        __syncthreads();

        // ---- compute 8x8 microtile over BK k-steps ----
        #pragma unroll
        for (int kk = 0; kk < BK; kk++) {
            float a[8], b[8];
            float4 a0 = *reinterpret_cast<const float4*>(&As[kk][ty * 8]);
            float4 a1 = *reinterpret_cast<const float4*>(&As[kk][ty * 8 + 4]);
            float4 b0 = *reinterpret_cast<const float4*>(&Bs[kk][tx * 8]);
            float4 b1 = *reinterpret_cast<const float4*>(&Bs[kk][tx * 8 + 4]);
            a[0] = a0.x; a[1] = a0.y; a[2] = a0.z; a[3] = a0.w;
            a[4] = a1.x; a[5] = a1.y; a[6] = a1.z; a[7] = a1.w;
            b[0] = b0.x; b[1] = b0.y; b[2] = b0.z; b[3] = b0.w;
            b[4] = b1.x; b[5] = b1.y; b[6] = b1.z; b[7] = b1.w;
            #pragma unroll
            for (int i = 0; i < 8; i++)
                #pragma unroll
                for (int j = 0; j < 8; j++)
                    acc[i][j] = fmaf(a[i], b[j], acc[i][j]);
        }

        __syncthreads();
    }

    // ---- epilogue: bias + mask, vectorized stores ----
    float bb[8];
    #pragma unroll
    for (int j = 0; j < 8; j++) bb[j] = g_bias[col0 + tx * 8 + j];

    #pragma unroll
    for (int i = 0; i < 8; i++) {
        int rr = row0 + ty * 8 + i;
        bool on = (mask[rr] != 0u);
        float4 o0, o1;
        if (on) {
            o0.x = acc[i][0] + bb[0]; o0.y = acc[i][1] + bb[1];
            o0.z = acc[i][2] + bb[2]; o0.w = acc[i][3] + bb[3];
            o1.x = acc[i][4] + bb[4]; o1.y = acc[i][5] + bb[5];
            o1.z = acc[i][6] + bb[6]; o1.w = acc[i][7] + bb[7];
        } else {
            o0 = make_float4(0.f, 0.f, 0.f, 0.f);
            o1 = o0;
        }
        float* dst = out + rr * TOK + col0 + tx * 8;
        *reinterpret_cast<float4*>(dst)     = o0;
        *reinterpret_cast<float4*>(dst + 4) = o1;
    }
}

// ---------------------------------------------------------------------------
extern "C" void kernel_launch(void* const* d_in, const int* in_sizes, int n_in,
                              void* d_out, int out_size)
{
    const float*        emb   = (const float*)d_in[0];
    const float*        vis   = (const float*)d_in[1];
    const float*        bbox  = (const float*)d_in[2];
    const float*        kp    = (const float*)d_in[3];
    const unsigned int* mask  = (const unsigned int*)d_in[4];
    const float*        app_W = (const float*)d_in[5];
    const float*        app_b = (const float*)d_in[6];
    const float*        st_W  = (const float*)d_in[7];
    const float*        st_b  = (const float*)d_in[8];
    float*              out   = (float*)d_out;

    prep_kernel<<<512, 256>>>(app_W, app_b, st_W, st_b);

    dim3 grid(TOK / BN, M_ROWS / BM);   // (8, 256): col-tiles fastest -> A reuse in L2
    gemm_kernel<<<grid, 256>>>(emb, vis, bbox, kp, mask, out);
}